// round 1
// baseline (speedup 1.0000x reference)
#include <cuda_runtime.h>
#include <cstdint>

// ---------------- problem constants ----------------
#define Hh 80
#define Ww 80
#define NN 6400          // H*W
#define CC 6             // channels
#define LL 6             // labels
#define CLr 36           // LL*CC stacked rows
#define NITER 5

#define INV2G2 (1.0f/18.0f)     // 1/(2*3^2)      spatial-only
#define INV2A2 (1.0f/128.0f)    // 1/(2*8^2)      bilateral spatial
#define INV2B2 (1.0f/0.045f)    // 1/(2*0.15^2)   bilateral feature

// ---------------- GEMM tiling ----------------
#define KS 16            // k-split factor
#define KCHUNK 400       // 6400/KS
#define KT 100           // staged k-tile
#define RB 12            // rows per block (3 row-groups cover 36)
#define JT 1024          // columns per block (128 thr * 8 cols)

// ---------------- device scratch (no allocations allowed) ----------------
__device__ float g_Kb[(size_t)NN * NN];          // 164 MB bilateral kernel
__device__ float g_normb[NN];
__device__ float g_norms[NN];
__device__ float g_G[Hh * Hh];                   // 1-D spatial gaussian (theta_gamma)
__device__ float g_unary[CC * NN];
__device__ float g_q[CLr * NN];
__device__ float g_sm[CLr * NN];
__device__ float g_tmp[CLr * NN];
__device__ float g_Ssp[CLr * NN];
__device__ float g_msg[CLr * NN];
__device__ float g_part[(size_t)KS * CLr * NN];  // 14.7 MB GEMM partials

// ---------------- small setup: G, norm_s ----------------
__global__ void k_setup() {
    __shared__ float rowg[Hh];
    int tid = threadIdx.x;
    for (int i = tid; i < Hh * Hh; i += blockDim.x) {
        float d = (float)(i / Hh) - (float)(i % Hh);
        g_G[i] = __expf(-d * d * INV2G2);
    }
    __syncthreads();
    if (tid < Hh) {
        float s = 0.f;
        for (int b = 0; b < Hh; b++) s += g_G[tid * Hh + b];
        rowg[tid] = s;
    }
    __syncthreads();
    for (int i = tid; i < NN; i += blockDim.x)
        g_norms[i] = rowg[i / Ww] * rowg[i % Ww];
}

// ---------------- build bilateral kernel ----------------
__global__ void k_build(const float* __restrict__ feat) {
    int i = blockIdx.y;
    int j = blockIdx.x * blockDim.x + threadIdx.x;   // grid covers exactly NN
    float yi = (float)(i / Ww), xi = (float)(i % Ww);
    float yj = (float)(j / Ww), xj = (float)(j % Ww);
    float f0 = feat[3 * i], f1 = feat[3 * i + 1], f2 = feat[3 * i + 2];
    float e0 = feat[3 * j], e1 = feat[3 * j + 1], e2 = feat[3 * j + 2];
    float dy = yi - yj, dx = xi - xj;
    float d0 = f0 - e0, d1 = f1 - e1, d2 = f2 - e2;
    float arg = -(dy * dy + dx * dx) * INV2A2 - (d0 * d0 + d1 * d1 + d2 * d2) * INV2B2;
    g_Kb[(size_t)i * NN + j] = __expf(arg);
}

// ---------------- deterministic row sums of Kb ----------------
__global__ void k_rowsum() {
    int warp = (blockIdx.x * blockDim.x + threadIdx.x) >> 5;
    int lane = threadIdx.x & 31;
    if (warp >= NN) return;
    const float* row = g_Kb + (size_t)warp * NN;
    float s = 0.f;
    for (int j = lane; j < NN; j += 32) s += row[j];
    for (int o = 16; o; o >>= 1) s += __shfl_xor_sync(0xffffffffu, s, o);
    if (!lane) g_normb[warp] = s;
}

// ---------------- init: transpose unary, replicate q over labels ----------------
__global__ void k_init(const float* __restrict__ un) {
    int idx = blockIdx.x * blockDim.x + threadIdx.x;
    if (idx >= CC * NN) return;
    int c = idx / NN, n = idx - c * NN;
    float u = un[n * CC + c];
    g_unary[idx] = u;
#pragma unroll
    for (int l = 0; l < LL; l++) g_q[(size_t)l * CC * NN + idx] = u;
}

// ---------------- softmax over channels ----------------
__global__ void k_softmax() {
    int idx = blockIdx.x * blockDim.x + threadIdx.x;
    if (idx >= LL * NN) return;
    int l = idx / NN, n = idx - l * NN;
    size_t base = (size_t)l * CC * NN + n;
    float v[CC], mx = -1e30f;
#pragma unroll
    for (int c = 0; c < CC; c++) { v[c] = g_q[base + (size_t)c * NN]; mx = fmaxf(mx, v[c]); }
    float s = 0.f;
#pragma unroll
    for (int c = 0; c < CC; c++) { v[c] = __expf(v[c] - mx); s += v[c]; }
    float inv = 1.f / s;
#pragma unroll
    for (int c = 0; c < CC; c++) g_sm[base + (size_t)c * NN] = v[c] * inv;
}

// ---------------- separable spatial filter: pass over y ----------------
__global__ void k_spat1() {
    int idx = blockIdx.x * blockDim.x + threadIdx.x;
    if (idx >= CLr * NN) return;
    int r = idx / NN, rem = idx - r * NN;
    int y = rem / Ww, x = rem - y * Ww;
    const float* src = g_sm + (size_t)r * NN + x;
    const float* grow = g_G + y * Hh;
    float s = 0.f;
#pragma unroll 4
    for (int yp = 0; yp < Hh; yp++) s += grow[yp] * src[(size_t)yp * Ww];
    g_tmp[idx] = s;
}

// ---------------- separable spatial filter: pass over x + normalize ----------------
__global__ void k_spat2() {
    int idx = blockIdx.x * blockDim.x + threadIdx.x;
    if (idx >= CLr * NN) return;
    int r = idx / NN, rem = idx - r * NN;
    int y = rem / Ww, x = rem - y * Ww;
    const float* src = g_tmp + (size_t)r * NN + (size_t)y * Ww;
    const float* grow = g_G + x * Hh;
    float s = 0.f;
#pragma unroll 4
    for (int xp = 0; xp < Hh; xp++) s += grow[xp] * src[xp];
    g_Ssp[idx] = s / g_norms[rem];
}

// ---------------- bilateral GEMM: [36 x 6400] @ [6400 x 6400], k-split partials ----------------
__global__ __launch_bounds__(128) void k_gemm() {
    __shared__ unsigned long long s_a[RB * KT];   // sm values duplicated into f32x2 pairs
    int tid = threadIdx.x;
    int jbase = blockIdx.x * JT;
    int r0 = blockIdx.y * RB;
    int kbase = blockIdx.z * KCHUNK;
    int c0 = jbase + 4 * tid;
    int c1 = c0 + 512;
    bool v0 = (c0 < NN), v1 = (c1 < NN);

    unsigned long long acc[RB][4];
#pragma unroll
    for (int rr = 0; rr < RB; rr++)
#pragma unroll
        for (int p = 0; p < 4; p++) acc[rr][p] = 0ull;

    for (int t = 0; t < KCHUNK / KT; t++) {
        int kt0 = kbase + t * KT;
        for (int e = tid; e < RB * KT; e += 128) {
            int rr = e / KT, kk = e - rr * KT;
            float v = g_sm[(size_t)(r0 + rr) * NN + kt0 + kk];
            unsigned long long pv;
            asm("mov.b64 %0, {%1, %1};" : "=l"(pv) : "f"(v));
            s_a[e] = pv;
        }
        __syncthreads();
#pragma unroll 4
        for (int kk = 0; kk < KT; kk++) {
            size_t rowoff = (size_t)(kt0 + kk) * NN;
            float4 b0 = v0 ? *(const float4*)(g_Kb + rowoff + c0) : make_float4(0.f, 0.f, 0.f, 0.f);
            float4 b1 = v1 ? *(const float4*)(g_Kb + rowoff + c1) : make_float4(0.f, 0.f, 0.f, 0.f);
            unsigned long long B0, B1, B2, B3;
            asm("mov.b64 %0, {%1, %2};" : "=l"(B0) : "f"(b0.x), "f"(b0.y));
            asm("mov.b64 %0, {%1, %2};" : "=l"(B1) : "f"(b0.z), "f"(b0.w));
            asm("mov.b64 %0, {%1, %2};" : "=l"(B2) : "f"(b1.x), "f"(b1.y));
            asm("mov.b64 %0, {%1, %2};" : "=l"(B3) : "f"(b1.z), "f"(b1.w));
#pragma unroll
            for (int rr = 0; rr < RB; rr++) {
                unsigned long long A = s_a[rr * KT + kk];
                asm("fma.rn.f32x2 %0, %1, %2, %0;" : "+l"(acc[rr][0]) : "l"(A), "l"(B0));
                asm("fma.rn.f32x2 %0, %1, %2, %0;" : "+l"(acc[rr][1]) : "l"(A), "l"(B1));
                asm("fma.rn.f32x2 %0, %1, %2, %0;" : "+l"(acc[rr][2]) : "l"(A), "l"(B2));
                asm("fma.rn.f32x2 %0, %1, %2, %0;" : "+l"(acc[rr][3]) : "l"(A), "l"(B3));
            }
        }
        __syncthreads();
    }
    // write partials
#pragma unroll
    for (int rr = 0; rr < RB; rr++) {
        size_t base = ((size_t)blockIdx.z * CLr + (r0 + rr)) * NN;
        if (v0) {
            float4 o;
            asm("mov.b64 {%0, %1}, %2;" : "=f"(o.x), "=f"(o.y) : "l"(acc[rr][0]));
            asm("mov.b64 {%0, %1}, %2;" : "=f"(o.z), "=f"(o.w) : "l"(acc[rr][1]));
            *(float4*)(g_part + base + c0) = o;
        }
        if (v1) {
            float4 o;
            asm("mov.b64 {%0, %1}, %2;" : "=f"(o.x), "=f"(o.y) : "l"(acc[rr][2]));
            asm("mov.b64 {%0, %1}, %2;" : "=f"(o.z), "=f"(o.w) : "l"(acc[rr][3]));
            *(float4*)(g_part + base + c1) = o;
        }
    }
}

// ---------------- reduce partials, mix C x C weights, update q ----------------
__global__ void k_update(const float* __restrict__ Wcomp, const float* __restrict__ WLG,
                         const float* __restrict__ Wsp, const float* __restrict__ Wbl) {
    __shared__ float sC[36], sL[36], sS[36], sB[36];
    int tid = threadIdx.x;
    if (tid < 36) { sC[tid] = Wcomp[tid]; sL[tid] = WLG[tid]; sS[tid] = Wsp[tid]; sB[tid] = Wbl[tid]; }
    __syncthreads();
    int idx = blockIdx.x * blockDim.x + tid;
    if (idx >= LL * NN) return;
    int l = idx / NN, n = idx - l * NN;
    float nb = g_normb[n];
    float ssp[CC], sb[CC];
#pragma unroll
    for (int c2 = 0; c2 < CC; c2++) {
        size_t ro = (size_t)(l * CC + c2) * NN + n;
        ssp[c2] = g_Ssp[ro];
        float s = 0.f;
#pragma unroll
        for (int z = 0; z < KS; z++) s += g_part[(size_t)z * CLr * NN + ro];
        sb[c2] = s / nb;
    }
    float msg[CC];
#pragma unroll
    for (int c = 0; c < CC; c++) {
        float m = 0.f;
#pragma unroll
        for (int c2 = 0; c2 < CC; c2++)
            m += sS[c * CC + c2] * ssp[c2] + sB[c * CC + c2] * sb[c2];
        msg[c] = m;
        g_msg[(size_t)(l * CC + c) * NN + n] = m;
    }
#pragma unroll
    for (int c = 0; c < CC; c++) {
        float pw = 0.f;
#pragma unroll
        for (int c2 = 0; c2 < CC; c2++) pw += sC[c * CC + c2] * msg[c2];
        g_q[(size_t)(l * CC + c) * NN + n] = g_unary[c * NN + n] + sL[c * CC + l] - pw;
    }
}

// ---------------- final ELBO per label (deterministic block reduction) ----------------
__global__ void k_elbo(const float* __restrict__ WLG, float* __restrict__ out) {
    __shared__ float sL[36];
    __shared__ float red[256];
    int l = blockIdx.x, tid = threadIdx.x;
    if (tid < 36) sL[tid] = WLG[tid];
    __syncthreads();
    float acc = 0.f;
    for (int i = tid; i < CC * NN; i += 256) {
        int c = i / NN;
        float s = g_sm[(size_t)l * CC * NN + i];
        float u = g_unary[i];
        float m = g_msg[(size_t)l * CC * NN + i];
        acc += s * (u + sL[c * CC + l] - m) - s * __logf(s + 1e-10f);
    }
    red[tid] = acc;
    __syncthreads();
    for (int o = 128; o; o >>= 1) {
        if (tid < o) red[tid] += red[tid + o];
        __syncthreads();
    }
    if (!tid) out[l] = red[0];
}

// ---------------- launch ----------------
extern "C" void kernel_launch(void* const* d_in, const int* in_sizes, int n_in,
                              void* d_out, int out_size) {
    const float* unary = (const float*)d_in[0];   // [1,80,80,6]
    const float* feat  = (const float*)d_in[1];   // [80,80,3]
    const float* Wcomp = (const float*)d_in[2];   // [6,6]
    const float* WLG   = (const float*)d_in[3];   // [6,6]
    const float* Wsp   = (const float*)d_in[4];   // [6,6]
    const float* Wbl   = (const float*)d_in[5];   // [6,6]
    float* out = (float*)d_out;                   // [6]

    k_setup<<<1, 256>>>();
    k_build<<<dim3(NN / 256, NN), 256>>>(feat);
    k_rowsum<<<(NN * 32 + 255) / 256, 256>>>();
    k_init<<<(CC * NN + 255) / 256, 256>>>(unary);

    for (int it = 0; it < NITER; it++) {
        k_softmax<<<(LL * NN + 255) / 256, 256>>>();
        k_spat1<<<(CLr * NN + 255) / 256, 256>>>();
        k_spat2<<<(CLr * NN + 255) / 256, 256>>>();
        k_gemm<<<dim3((NN + JT - 1) / JT, CLr / RB, KS), 128>>>();
        k_update<<<(LL * NN + 255) / 256, 256>>>(Wcomp, WLG, Wsp, Wbl);
    }
    k_elbo<<<LL, 256>>>(WLG, out);
}

// round 3
// speedup vs baseline: 1.8590x; 1.8590x over previous
#include <cuda_runtime.h>
#include <cuda_fp16.h>
#include <cstdint>

// ---------------- problem constants ----------------
#define Hh 80
#define Ww 80
#define NN 6400          // H*W
#define CC 6             // channels
#define LL 6             // labels
#define CR 30            // 5 rows per label; 6th reconstructed from sum-to-one
#define NITER 5

#define INV2G2 (1.0f/18.0f)     // 1/(2*3^2)
#define INV2A2 (1.0f/128.0f)    // 1/(2*8^2)
#define INV2B2 (1.0f/0.045f)    // 1/(2*0.15^2)

// ---------------- GEMM tiling ----------------
#define KSPLIT 20
#define KCHUNK 320       // 6400 / 20
#define KT 80            // staged k-tile (4 stages per chunk)
#define JT 512           // 256 threads * 2 cols
#define JBLK 13          // ceil(6400/512), last block half-valid

// ---------------- build tiling ----------------
#define BROWS 8          // i-rows per build block
#define TJ 800           // staged pixel tile (8 tiles exactly)

typedef unsigned long long ull;

// ---------------- device scratch ----------------
__device__ __half g_Kbh[(size_t)NN * NN];        // 82 MB bilateral kernel (fp16)
__device__ float  g_normb[NN];
__device__ float  g_norms[NN];
__device__ float  g_G[Hh * Hh];
__device__ float4 g_pix0[NN];                    // (y*ca, x*ca, f0*cb, f1*cb)
__device__ float  g_pix1[NN];                    // f2*cb
__device__ float  g_unary[CC * NN];
__device__ float  g_q[LL * CC * NN];
__device__ float  g_sm[LL * CC * NN];
__device__ float  g_tmp[CR * NN];
__device__ float  g_Ssp[CR * NN];
__device__ float  g_msg[LL * CC * NN];
__device__ float  g_part[(size_t)KSPLIT * CR * NN];   // 15.4 MB partials

// ---------------- setup: G table, norms, pixel attribute vectors ----------------
__global__ void k_setup(const float* __restrict__ feat) {
    __shared__ float rowg[Hh];
    int tid = threadIdx.x;
    for (int i = tid; i < Hh * Hh; i += 256) {
        float d = (float)(i / Hh) - (float)(i % Hh);
        g_G[i] = __expf(-d * d * INV2G2);
    }
    __syncthreads();
    if (tid < Hh) {
        float s = 0.f;
        for (int b = 0; b < Hh; b++) s += g_G[tid * Hh + b];
        rowg[tid] = s;
    }
    __syncthreads();
    const float ca = sqrtf(INV2A2), cb = sqrtf(INV2B2);
    for (int i = tid; i < NN; i += 256) {
        int y = i / Ww, x = i - y * Ww;
        g_norms[i] = rowg[y] * rowg[x];
        float f0 = feat[3 * i], f1 = feat[3 * i + 1], f2 = feat[3 * i + 2];
        g_pix0[i] = make_float4((float)y * ca, (float)x * ca, f0 * cb, f1 * cb);
        g_pix1[i] = f2 * cb;
    }
}

// ---------------- init: transpose unary, replicate q over labels ----------------
__global__ void k_init(const float* __restrict__ un) {
    int idx = blockIdx.x * blockDim.x + threadIdx.x;
    if (idx >= CC * NN) return;
    int c = idx / NN, n = idx - c * NN;
    float u = un[n * CC + c];
    g_unary[idx] = u;
#pragma unroll
    for (int l = 0; l < LL; l++) g_q[(size_t)l * CC * NN + idx] = u;
}

// ---------------- build Kb (fp16) + row sums, fused; 8 rows per block ----------------
__global__ __launch_bounds__(256) void k_build() {
    __shared__ float4 s_p0[TJ];
    __shared__ float  s_p1[TJ];
    __shared__ float  red[256];
    int tid = threadIdx.x;
    int i0 = blockIdx.x * BROWS;

    float4 p0[BROWS]; float p1[BROWS];
#pragma unroll
    for (int r = 0; r < BROWS; r++) { p0[r] = g_pix0[i0 + r]; p1[r] = g_pix1[i0 + r]; }

    float rsum[BROWS];
#pragma unroll
    for (int r = 0; r < BROWS; r++) rsum[r] = 0.f;

    for (int jt = 0; jt < NN; jt += TJ) {
        for (int e = tid; e < TJ; e += 256) {
            s_p0[e] = g_pix0[jt + e];
            s_p1[e] = g_pix1[jt + e];
        }
        __syncthreads();
        for (int jj = tid; jj < TJ / 2; jj += 256) {
            float4 qa = s_p0[2 * jj],  qb = s_p0[2 * jj + 1];
            float  ra = s_p1[2 * jj],  rb = s_p1[2 * jj + 1];
            int jph = (jt >> 1) + jj;   // half2 index within row
#pragma unroll
            for (int r = 0; r < BROWS; r++) {
                float d0 = p0[r].x - qa.x, d1 = p0[r].y - qa.y, d2 = p0[r].z - qa.z,
                      d3 = p0[r].w - qa.w, d4 = p1[r] - ra;
                float va = __expf(-(d0*d0 + d1*d1 + d2*d2 + d3*d3 + d4*d4));
                d0 = p0[r].x - qb.x; d1 = p0[r].y - qb.y; d2 = p0[r].z - qb.z;
                d3 = p0[r].w - qb.w; d4 = p1[r] - rb;
                float vb = __expf(-(d0*d0 + d1*d1 + d2*d2 + d3*d3 + d4*d4));
                __half ha = __float2half_rn(va), hb = __float2half_rn(vb);
                // accumulate the ROUNDED values so normb matches the GEMM input
                rsum[r] += __half2float(ha) + __half2float(hb);
                ((__half2*)(g_Kbh + (size_t)(i0 + r) * NN))[jph] = __halves2half2(ha, hb);
            }
        }
        __syncthreads();
    }
#pragma unroll
    for (int r = 0; r < BROWS; r++) {
        red[tid] = rsum[r];
        __syncthreads();
        for (int o = 128; o; o >>= 1) {
            if (tid < o) red[tid] += red[tid + o];
            __syncthreads();
        }
        if (!tid) g_normb[i0 + r] = red[0];
        __syncthreads();
    }
}

// ---------------- softmax over channels (full 36 rows; GEMM uses 30) ----------------
__global__ void k_softmax() {
    int idx = blockIdx.x * blockDim.x + threadIdx.x;
    if (idx >= LL * NN) return;
    int l = idx / NN, n = idx - l * NN;
    size_t base = (size_t)l * CC * NN + n;
    float v[CC], mx = -1e30f;
#pragma unroll
    for (int c = 0; c < CC; c++) { v[c] = g_q[base + (size_t)c * NN]; mx = fmaxf(mx, v[c]); }
    float s = 0.f;
#pragma unroll
    for (int c = 0; c < CC; c++) { v[c] = __expf(v[c] - mx); s += v[c]; }
    float inv = 1.f / s;
#pragma unroll
    for (int c = 0; c < CC; c++) g_sm[base + (size_t)c * NN] = v[c] * inv;
}

// row r (0..29) -> g_sm row (skip every 6th channel)
__device__ __forceinline__ int rowmap(int r) { return (r / 5) * CC + (r % 5); }

// ---------------- separable spatial filter: y pass ----------------
__global__ void k_spat1() {
    int idx = blockIdx.x * blockDim.x + threadIdx.x;
    if (idx >= CR * NN) return;
    int r = idx / NN, rem = idx - r * NN;
    int y = rem / Ww, x = rem - y * Ww;
    const float* src = g_sm + (size_t)rowmap(r) * NN + x;
    const float* grow = g_G + y * Hh;
    float s = 0.f;
#pragma unroll 4
    for (int yp = 0; yp < Hh; yp++) s += grow[yp] * src[(size_t)yp * Ww];
    g_tmp[idx] = s;
}

// ---------------- x pass + normalize ----------------
__global__ void k_spat2() {
    int idx = blockIdx.x * blockDim.x + threadIdx.x;
    if (idx >= CR * NN) return;
    int r = idx / NN, rem = idx - r * NN;
    int y = rem / Ww, x = rem - y * Ww;
    const float* src = g_tmp + (size_t)r * NN + (size_t)y * Ww;
    const float* grow = g_G + x * Hh;
    float s = 0.f;
#pragma unroll 4
    for (int xp = 0; xp < Hh; xp++) s += grow[xp] * src[xp];
    g_Ssp[idx] = s / g_norms[rem];
}

// ---------------- bilateral GEMM: [30 x 6400] @ fp16[6400 x 6400] ----------------
// One block: ALL 30 rows x 512 cols x 320 k's. f32x2 accumulate over column pairs.
__global__ __launch_bounds__(256, 2) void k_gemm() {
    __shared__ __align__(16) ull s_a[KT * CR];    // sm duplicated into f32x2 pairs
    int tid = threadIdx.x;
    int c0 = blockIdx.x * JT + 2 * tid;
    int kbase = blockIdx.y * KCHUNK;
    bool v = (c0 < NN);
    const __half2* Kb2 = (const __half2*)g_Kbh;
    int cph = c0 >> 1;

    ull acc[CR];
#pragma unroll
    for (int rr = 0; rr < CR; rr++) acc[rr] = 0ull;

    for (int t = 0; t < KCHUNK / KT; t++) {
        int k0 = kbase + t * KT;
        for (int e = tid; e < KT * CR; e += 256) {
            int kk = e / CR, rr = e - kk * CR;
            float a = g_sm[(size_t)rowmap(rr) * NN + k0 + kk];
            ull pv;
            asm("mov.b64 %0, {%1, %1};" : "=l"(pv) : "f"(a));
            s_a[e] = pv;
        }
        __syncthreads();
#pragma unroll 4
        for (int kk = 0; kk < KT; kk++) {
            __half2 hb = v ? Kb2[(size_t)(k0 + kk) * (NN / 2) + cph]
                           : __halves2half2(__float2half_rn(0.f), __float2half_rn(0.f));
            float2 fb = __half22float2(hb);
            ull B;
            asm("mov.b64 %0, {%1, %2};" : "=l"(B) : "f"(fb.x), "f"(fb.y));
            const ull* arow = s_a + kk * CR;
#pragma unroll
            for (int rp = 0; rp < CR / 2; rp++) {
                ulonglong2 A = *(const ulonglong2*)(arow + 2 * rp);
                asm("fma.rn.f32x2 %0, %1, %2, %0;" : "+l"(acc[2 * rp])     : "l"(A.x), "l"(B));
                asm("fma.rn.f32x2 %0, %1, %2, %0;" : "+l"(acc[2 * rp + 1]) : "l"(A.y), "l"(B));
            }
        }
        __syncthreads();
    }
    if (v) {
#pragma unroll
        for (int rr = 0; rr < CR; rr++) {
            float2 o;
            asm("mov.b64 {%0, %1}, %2;" : "=f"(o.x), "=f"(o.y) : "l"(acc[rr]));
            *(float2*)(g_part + ((size_t)blockIdx.y * CR + rr) * NN + c0) = o;
        }
    }
}

// ---------------- reduce partials, reconstruct 6th channel, mix weights, update q ----------------
__global__ void k_update(const float* __restrict__ Wcomp, const float* __restrict__ WLG,
                         const float* __restrict__ Wsp, const float* __restrict__ Wbl) {
    __shared__ float sC[36], sL[36], sS[36], sB[36];
    int tid = threadIdx.x;
    if (tid < 36) { sC[tid] = Wcomp[tid]; sL[tid] = WLG[tid]; sS[tid] = Wsp[tid]; sB[tid] = Wbl[tid]; }
    __syncthreads();
    int idx = blockIdx.x * blockDim.x + tid;
    if (idx >= LL * NN) return;
    int l = idx / NN, n = idx - l * NN;
    float invnb = 1.f / g_normb[n];
    float ssp[CC], sb[CC];
    float tsp = 0.f, tb = 0.f;
#pragma unroll
    for (int c2 = 0; c2 < 5; c2++) {
        size_t ro = (size_t)(l * 5 + c2) * NN + n;
        ssp[c2] = g_Ssp[ro];
        float s = 0.f;
#pragma unroll
        for (int z = 0; z < KSPLIT; z++) s += g_part[(size_t)z * CR * NN + ro];
        sb[c2] = s * invnb;
        tsp += ssp[c2]; tb += sb[c2];
    }
    // normalized filters of a distribution sum to 1 -> reconstruct channel 5
    ssp[5] = 1.f - tsp;
    sb[5] = 1.f - tb;
    float msg[CC];
#pragma unroll
    for (int c = 0; c < CC; c++) {
        float m = 0.f;
#pragma unroll
        for (int c2 = 0; c2 < CC; c2++)
            m += sS[c * CC + c2] * ssp[c2] + sB[c * CC + c2] * sb[c2];
        msg[c] = m;
        g_msg[(size_t)(l * CC + c) * NN + n] = m;
    }
#pragma unroll
    for (int c = 0; c < CC; c++) {
        float pw = 0.f;
#pragma unroll
        for (int c2 = 0; c2 < CC; c2++) pw += sC[c * CC + c2] * msg[c2];
        g_q[(size_t)(l * CC + c) * NN + n] = g_unary[c * NN + n] + sL[c * CC + l] - pw;
    }
}

// ---------------- final ELBO per label ----------------
__global__ void k_elbo(const float* __restrict__ WLG, float* __restrict__ out) {
    __shared__ float sL[36];
    __shared__ float red[256];
    int l = blockIdx.x, tid = threadIdx.x;
    if (tid < 36) sL[tid] = WLG[tid];
    __syncthreads();
    float acc = 0.f;
    for (int i = tid; i < CC * NN; i += 256) {
        int c = i / NN;
        float s = g_sm[(size_t)l * CC * NN + i];
        float u = g_unary[i];
        float m = g_msg[(size_t)l * CC * NN + i];
        acc += s * (u + sL[c * CC + l] - m) - s * __logf(s + 1e-10f);
    }
    red[tid] = acc;
    __syncthreads();
    for (int o = 128; o; o >>= 1) {
        if (tid < o) red[tid] += red[tid + o];
        __syncthreads();
    }
    if (!tid) out[l] = red[0];
}

// ---------------- launch ----------------
extern "C" void kernel_launch(void* const* d_in, const int* in_sizes, int n_in,
                              void* d_out, int out_size) {
    const float* unary = (const float*)d_in[0];
    const float* feat  = (const float*)d_in[1];
    const float* Wcomp = (const float*)d_in[2];
    const float* WLG   = (const float*)d_in[3];
    const float* Wsp   = (const float*)d_in[4];
    const float* Wbl   = (const float*)d_in[5];
    float* out = (float*)d_out;

    k_init<<<150, 256>>>(unary);
    k_setup<<<1, 256>>>(feat);
    k_build<<<NN / BROWS, 256>>>();

    for (int it = 0; it < NITER; it++) {
        k_softmax<<<150, 256>>>();
        k_spat1<<<CR * NN / 256, 256>>>();
        k_spat2<<<CR * NN / 256, 256>>>();
        k_gemm<<<dim3(JBLK, KSPLIT), 256>>>();
        k_update<<<150, 256>>>(Wcomp, WLG, Wsp, Wbl);
    }
    k_elbo<<<LL, 256>>>(WLG, out);
}

// round 4
// speedup vs baseline: 2.6609x; 1.4314x over previous
#include <cuda_runtime.h>
#include <cuda_fp16.h>
#include <cstdint>

// ---------------- problem constants ----------------
#define Hh 80
#define Ww 80
#define NN 6400
#define CC 6
#define LL 6
#define CR 30            // spatial path: 5 rows/label, 6th reconstructed
#define MR 36            // bilateral MMA real rows
#define MP 48            // padded M for m16 tiles
#define NITER 5

#define INV2G2 (1.0f/18.0f)
#define INV2A2 (1.0f/128.0f)
#define INV2B2 (1.0f/0.045f)

// ---------------- GEMM tiling ----------------
#define KSPLIT 10
#define KC 640           // K per block
#define JB 128           // cols per block (8 warps x n16)

// ---------------- build tiling ----------------
#define BROWS 8
#define TJ 800

typedef unsigned long long ull;

// ---------------- device scratch ----------------
__device__ __align__(16) __half g_Kbh[(size_t)NN * NN];   // 82 MB
__device__ __align__(16) __half g_smh[MP * NN];           // fp16 A (rows 36-47 junk, discarded)
__device__ float  g_normb[NN];
__device__ float  g_norms[NN];
__device__ float  g_G[Hh * Hh];
__device__ float4 g_pix0[NN];
__device__ float  g_pix1[NN];
__device__ float  g_unary[CC * NN];
__device__ float  g_q[LL * CC * NN];
__device__ float  g_sm[LL * CC * NN];
__device__ float  g_tmp[CR * NN];
__device__ float  g_Ssp[CR * NN];
__device__ float  g_msg[LL * CC * NN];
__device__ float  g_part[(size_t)KSPLIT * MR * NN];       // 9.2 MB

__device__ __forceinline__ unsigned su32(const void* p) {
    unsigned a;
    asm("{ .reg .u64 t; cvta.to.shared.u64 t, %1; cvt.u32.u64 %0, t; }" : "=r"(a) : "l"(p));
    return a;
}

// ---------------- setup: G table, norms, pixel vectors ----------------
__global__ void k_setup(const float* __restrict__ feat) {
    __shared__ float rowg[Hh];
    int tid = threadIdx.x;
    for (int i = tid; i < Hh * Hh; i += 256) {
        float d = (float)(i / Hh) - (float)(i % Hh);
        g_G[i] = __expf(-d * d * INV2G2);
    }
    __syncthreads();
    if (tid < Hh) {
        float s = 0.f;
        for (int b = 0; b < Hh; b++) s += g_G[tid * Hh + b];
        rowg[tid] = s;
    }
    __syncthreads();
    const float ca = sqrtf(INV2A2), cb = sqrtf(INV2B2);
    for (int i = tid; i < NN; i += 256) {
        int y = i / Ww, x = i - y * Ww;
        g_norms[i] = rowg[y] * rowg[x];
        float f0 = feat[3 * i], f1 = feat[3 * i + 1], f2 = feat[3 * i + 2];
        g_pix0[i] = make_float4((float)y * ca, (float)x * ca, f0 * cb, f1 * cb);
        g_pix1[i] = f2 * cb;
    }
}

// ---------------- build Kb (fp16) + row sums ----------------
__global__ __launch_bounds__(256) void k_build() {
    __shared__ float4 s_p0[TJ];
    __shared__ float  s_p1[TJ];
    __shared__ float  red[256];
    int tid = threadIdx.x;
    int i0 = blockIdx.x * BROWS;
    float4 p0[BROWS]; float p1[BROWS];
#pragma unroll
    for (int r = 0; r < BROWS; r++) { p0[r] = g_pix0[i0 + r]; p1[r] = g_pix1[i0 + r]; }
    float rsum[BROWS];
#pragma unroll
    for (int r = 0; r < BROWS; r++) rsum[r] = 0.f;

    for (int jt = 0; jt < NN; jt += TJ) {
        for (int e = tid; e < TJ; e += 256) { s_p0[e] = g_pix0[jt + e]; s_p1[e] = g_pix1[jt + e]; }
        __syncthreads();
        for (int jj = tid; jj < TJ / 2; jj += 256) {
            float4 qa = s_p0[2 * jj], qb = s_p0[2 * jj + 1];
            float  ra = s_p1[2 * jj], rb = s_p1[2 * jj + 1];
            int jph = (jt >> 1) + jj;
#pragma unroll
            for (int r = 0; r < BROWS; r++) {
                float d0 = p0[r].x - qa.x, d1 = p0[r].y - qa.y, d2 = p0[r].z - qa.z,
                      d3 = p0[r].w - qa.w, d4 = p1[r] - ra;
                float va = __expf(-(d0*d0 + d1*d1 + d2*d2 + d3*d3 + d4*d4));
                d0 = p0[r].x - qb.x; d1 = p0[r].y - qb.y; d2 = p0[r].z - qb.z;
                d3 = p0[r].w - qb.w; d4 = p1[r] - rb;
                float vb = __expf(-(d0*d0 + d1*d1 + d2*d2 + d3*d3 + d4*d4));
                __half ha = __float2half_rn(va), hb = __float2half_rn(vb);
                rsum[r] += __half2float(ha) + __half2float(hb);
                ((__half2*)(g_Kbh + (size_t)(i0 + r) * NN))[jph] = __halves2half2(ha, hb);
            }
        }
        __syncthreads();
    }
#pragma unroll
    for (int r = 0; r < BROWS; r++) {
        red[tid] = rsum[r];
        __syncthreads();
        for (int o = 128; o; o >>= 1) { if (tid < o) red[tid] += red[tid + o]; __syncthreads(); }
        if (!tid) g_normb[i0 + r] = red[0];
        __syncthreads();
    }
}

// ---------------- init: unary transpose + FIRST softmax (q == unary) ----------------
__global__ void k_init(const float* __restrict__ un) {
    int n = blockIdx.x * blockDim.x + threadIdx.x;
    if (n >= NN) return;
    float v[CC], mx = -1e30f;
#pragma unroll
    for (int c = 0; c < CC; c++) { v[c] = un[n * CC + c]; g_unary[c * NN + n] = v[c]; mx = fmaxf(mx, v[c]); }
    float s = 0.f;
#pragma unroll
    for (int c = 0; c < CC; c++) { v[c] = __expf(v[c] - mx); s += v[c]; }
    float inv = 1.f / s;
#pragma unroll
    for (int c = 0; c < CC; c++) {
        float p = v[c] * inv;
        __half ph = __float2half_rn(p);
#pragma unroll
        for (int l = 0; l < LL; l++) {
            g_sm[(size_t)(l * CC + c) * NN + n] = p;
            g_smh[(l * CC + c) * NN + n] = ph;
        }
    }
}

// ---------------- softmax over channels (iters 2..5) ----------------
__global__ void k_softmax() {
    int idx = blockIdx.x * blockDim.x + threadIdx.x;
    if (idx >= LL * NN) return;
    int l = idx / NN, n = idx - l * NN;
    size_t base = (size_t)l * CC * NN + n;
    float v[CC], mx = -1e30f;
#pragma unroll
    for (int c = 0; c < CC; c++) { v[c] = g_q[base + (size_t)c * NN]; mx = fmaxf(mx, v[c]); }
    float s = 0.f;
#pragma unroll
    for (int c = 0; c < CC; c++) { v[c] = __expf(v[c] - mx); s += v[c]; }
    float inv = 1.f / s;
#pragma unroll
    for (int c = 0; c < CC; c++) {
        float p = v[c] * inv;
        g_sm[base + (size_t)c * NN] = p;
        g_smh[(l * CC + c) * NN + n] = __float2half_rn(p);
    }
}

__device__ __forceinline__ int rowmap(int r) { return (r / 5) * CC + (r % 5); }

// ---------------- spatial filter passes ----------------
__global__ void k_spat1() {
    int idx = blockIdx.x * blockDim.x + threadIdx.x;
    if (idx >= CR * NN) return;
    int r = idx / NN, rem = idx - r * NN;
    int y = rem / Ww, x = rem - y * Ww;
    const float* src = g_sm + (size_t)rowmap(r) * NN + x;
    const float* grow = g_G + y * Hh;
    float s = 0.f;
#pragma unroll 4
    for (int yp = 0; yp < Hh; yp++) s += grow[yp] * src[(size_t)yp * Ww];
    g_tmp[idx] = s;
}

__global__ void k_spat2() {
    int idx = blockIdx.x * blockDim.x + threadIdx.x;
    if (idx >= CR * NN) return;
    int r = idx / NN, rem = idx - r * NN;
    int y = rem / Ww, x = rem - y * Ww;
    const float* src = g_tmp + (size_t)r * NN + (size_t)y * Ww;
    const float* grow = g_G + x * Hh;
    float s = 0.f;
#pragma unroll 4
    for (int xp = 0; xp < Hh; xp++) s += grow[xp] * src[xp];
    g_Ssp[idx] = s / g_norms[rem];
}

// ---------------- tensor-core bilateral GEMM ----------------
// C[48 x 6400] += A_f16[48 x K] * Kb_f16[K x 6400], k-split partials.
// Block: 256 thr (8 warps); warp w covers n16 = j0 + w*16; all warps do all 48 M rows.
__global__ __launch_bounds__(256, 3) void k_gemm() {
    __shared__ __align__(16) __half s_a[MP * 64];     // 6 KB, XOR-swizzled 16B chunks
    __shared__ __align__(16) __half s_b[64 * JB];     // 16 KB, XOR-swizzled
    int tid = threadIdx.x, w = tid >> 5, lane = tid & 31;
    int j0 = blockIdx.x * JB;
    int kbase = blockIdx.y * KC;
    unsigned sa0 = su32(s_a), sb0 = su32(s_b);

    float acc[3][2][4];
#pragma unroll
    for (int mt = 0; mt < 3; mt++)
#pragma unroll
        for (int nt = 0; nt < 2; nt++)
#pragma unroll
            for (int i = 0; i < 4; i++) acc[mt][nt][i] = 0.f;

    // ldmatrix lane-address components
    int lrow = ((lane >> 3) & 1) * 8 + (lane & 7);   // row-within-16 for A / k-within-16 for B
    int lhi  = (lane >> 4) & 1;                      // chunk parity

    for (int ko = 0; ko < KC / 64; ko++) {
        int k0 = kbase + ko * 64;
        // stage A: 48 rows x 8 chunks(16B)
        for (int e = tid; e < MP * 8; e += 256) {
            int r = e >> 3, c = e & 7;
            *(int4*)(s_a + r * 64 + ((c ^ (r & 7)) << 3)) =
                *(const int4*)(g_smh + (size_t)r * NN + k0 + c * 8);
        }
        // stage B: 64 k-rows x 16 chunks
        for (int e = tid; e < 64 * 16; e += 256) {
            int r = e >> 4, c = e & 15;
            *(int4*)(s_b + r * JB + ((c ^ (r & 7)) << 3)) =
                *(const int4*)(g_Kbh + (size_t)(k0 + r) * NN + j0 + c * 8);
        }
        __syncthreads();
#pragma unroll
        for (int kt = 0; kt < 4; kt++) {
            // B fragments: k16 x n16 via x4.trans
            unsigned b[4];
            {
                int kl = kt * 16 + lrow;
                int c = 2 * w + lhi;
                unsigned addr = sb0 + (unsigned)(kl * JB + ((c ^ (kl & 7)) << 3)) * 2u;
                asm volatile("ldmatrix.sync.aligned.m8n8.x4.trans.shared.b16 {%0,%1,%2,%3}, [%4];"
                             : "=r"(b[0]), "=r"(b[1]), "=r"(b[2]), "=r"(b[3]) : "r"(addr));
            }
#pragma unroll
            for (int mt = 0; mt < 3; mt++) {
                unsigned a[4];
                int r = mt * 16 + lrow;
                int c = kt * 2 + lhi;
                unsigned addr = sa0 + (unsigned)(r * 64 + ((c ^ (r & 7)) << 3)) * 2u;
                asm volatile("ldmatrix.sync.aligned.m8n8.x4.shared.b16 {%0,%1,%2,%3}, [%4];"
                             : "=r"(a[0]), "=r"(a[1]), "=r"(a[2]), "=r"(a[3]) : "r"(addr));
#pragma unroll
                for (int nt = 0; nt < 2; nt++) {
                    asm volatile(
                        "mma.sync.aligned.m16n8k16.row.col.f32.f16.f16.f32 "
                        "{%0,%1,%2,%3}, {%4,%5,%6,%7}, {%8,%9}, {%0,%1,%2,%3};"
                        : "+f"(acc[mt][nt][0]), "+f"(acc[mt][nt][1]),
                          "+f"(acc[mt][nt][2]), "+f"(acc[mt][nt][3])
                        : "r"(a[0]), "r"(a[1]), "r"(a[2]), "r"(a[3]),
                          "r"(b[2 * nt]), "r"(b[2 * nt + 1]));
                }
            }
        }
        __syncthreads();
    }
    // store partials (rows >= 36 discarded)
#pragma unroll
    for (int mt = 0; mt < 3; mt++) {
#pragma unroll
        for (int nt = 0; nt < 2; nt++) {
            int row = mt * 16 + (lane >> 2);
            int col = j0 + w * 16 + nt * 8 + (lane & 3) * 2;
            if (row < MR)
                *(float2*)(g_part + ((size_t)blockIdx.y * MR + row) * NN + col) =
                    make_float2(acc[mt][nt][0], acc[mt][nt][1]);
            if (row + 8 < MR)
                *(float2*)(g_part + ((size_t)blockIdx.y * MR + row + 8) * NN + col) =
                    make_float2(acc[mt][nt][2], acc[mt][nt][3]);
        }
    }
}

// ---------------- reduce partials, mix weights, update q ----------------
__global__ void k_update(const float* __restrict__ Wcomp, const float* __restrict__ WLG,
                         const float* __restrict__ Wsp, const float* __restrict__ Wbl) {
    __shared__ float sC[36], sL[36], sS[36], sB[36];
    int tid = threadIdx.x;
    if (tid < 36) { sC[tid] = Wcomp[tid]; sL[tid] = WLG[tid]; sS[tid] = Wsp[tid]; sB[tid] = Wbl[tid]; }
    __syncthreads();
    int idx = blockIdx.x * blockDim.x + tid;
    if (idx >= LL * NN) return;
    int l = idx / NN, n = idx - l * NN;
    float invnb = 1.f / g_normb[n];
    float ssp[CC], sb[CC];
    float tsp = 0.f;
#pragma unroll
    for (int c2 = 0; c2 < CC; c2++) {
        size_t ro = (size_t)(l * CC + c2) * NN + n;
        float s = 0.f;
#pragma unroll
        for (int z = 0; z < KSPLIT; z++) s += g_part[(size_t)z * MR * NN + ro];
        sb[c2] = s * invnb;
    }
#pragma unroll
    for (int c2 = 0; c2 < 5; c2++) {
        ssp[c2] = g_Ssp[(size_t)(l * 5 + c2) * NN + n];
        tsp += ssp[c2];
    }
    ssp[5] = 1.f - tsp;   // spatial-normalized distribution sums to 1
    float msg[CC];
#pragma unroll
    for (int c = 0; c < CC; c++) {
        float m = 0.f;
#pragma unroll
        for (int c2 = 0; c2 < CC; c2++)
            m += sS[c * CC + c2] * ssp[c2] + sB[c * CC + c2] * sb[c2];
        msg[c] = m;
        g_msg[(size_t)(l * CC + c) * NN + n] = m;
    }
#pragma unroll
    for (int c = 0; c < CC; c++) {
        float pw = 0.f;
#pragma unroll
        for (int c2 = 0; c2 < CC; c2++) pw += sC[c * CC + c2] * msg[c2];
        g_q[(size_t)(l * CC + c) * NN + n] = g_unary[c * NN + n] + sL[c * CC + l] - pw;
    }
}

// ---------------- final ELBO ----------------
__global__ void k_elbo(const float* __restrict__ WLG, float* __restrict__ out) {
    __shared__ float sL[36];
    __shared__ float red[256];
    int l = blockIdx.x, tid = threadIdx.x;
    if (tid < 36) sL[tid] = WLG[tid];
    __syncthreads();
    float acc = 0.f;
    for (int i = tid; i < CC * NN; i += 256) {
        int c = i / NN;
        float s = g_sm[(size_t)l * CC * NN + i];
        float u = g_unary[i];
        float m = g_msg[(size_t)l * CC * NN + i];
        acc += s * (u + sL[c * CC + l] - m) - s * __logf(s + 1e-10f);
    }
    red[tid] = acc;
    __syncthreads();
    for (int o = 128; o; o >>= 1) { if (tid < o) red[tid] += red[tid + o]; __syncthreads(); }
    if (!tid) out[l] = red[0];
}

// ---------------- launch ----------------
extern "C" void kernel_launch(void* const* d_in, const int* in_sizes, int n_in,
                              void* d_out, int out_size) {
    const float* unary = (const float*)d_in[0];
    const float* feat  = (const float*)d_in[1];
    const float* Wcomp = (const float*)d_in[2];
    const float* WLG   = (const float*)d_in[3];
    const float* Wsp   = (const float*)d_in[4];
    const float* Wbl   = (const float*)d_in[5];
    float* out = (float*)d_out;

    k_setup<<<1, 256>>>(feat);                 // launch 1
    k_build<<<NN / BROWS, 256>>>();            // launch 2
    k_init<<<25, 256>>>(unary);                // launch 3 (includes first softmax)

    for (int it = 0; it < NITER; it++) {
        if (it > 0) k_softmax<<<150, 256>>>();
        k_gemm<<<dim3(NN / JB, KSPLIT), 256>>>();    // launch 4 on it==0 -> profiled
        k_spat1<<<CR * NN / 256, 256>>>();
        k_spat2<<<CR * NN / 256, 256>>>();
        k_update<<<150, 256>>>(Wcomp, WLG, Wsp, Wbl);
    }
    k_elbo<<<LL, 256>>>(WLG, out);
}

// round 7
// speedup vs baseline: 2.9062x; 1.0922x over previous
#include <cuda_runtime.h>
#include <cuda_fp16.h>
#include <cstdint>

// ---------------- problem constants ----------------
#define Hh 80
#define Ww 80
#define NN 6400
#define CC 6
#define LL 6
#define CR 30            // spatial path rows (6th channel reconstructed)
#define MR 36            // bilateral MMA real rows
#define MP 48            // padded M
#define NITER 5

#define INV2G2 (1.0f/18.0f)
#define INV2A2 (1.0f/128.0f)
#define INV2B2 (1.0f/0.045f)

// ---------------- GEMM tiling ----------------
#define KSPLIT 20
#define KC 320           // K per block
#define NST 5            // KC/64 stages
#define JB 128           // cols per block

// ---------------- build tiling ----------------
#define BROWS 8
#define TJ 800

// ---------------- device scratch ----------------
__device__ __align__(16) __half g_Kbh[(size_t)NN * NN];   // 82 MB
__device__ __align__(16) __half g_smh[MP * NN];           // fp16 A (rows 36..47 junk)
__device__ float  g_normb[NN];
__device__ float  g_norms[NN];
__device__ float  g_G[Hh * Hh];
__device__ float4 g_pix0[NN];
__device__ float  g_pix1[NN];
__device__ float  g_unary[CC * NN];
__device__ float  g_sm[LL * CC * NN];
__device__ float  g_Ssp[CR * NN];
__device__ float  g_msg[LL * CC * NN];
__device__ float  g_part[(size_t)KSPLIT * MR * NN];       // 18.4 MB

__device__ __forceinline__ unsigned su32(const void* p) {
    unsigned a;
    asm("{ .reg .u64 t; cvta.to.shared.u64 t, %1; cvt.u32.u64 %0, t; }" : "=r"(a) : "l"(p));
    return a;
}
__device__ __forceinline__ void cpa16(unsigned dst, const void* src) {
    asm volatile("cp.async.cg.shared.global [%0], [%1], 16;" :: "r"(dst), "l"(src));
}

// ---------------- setup ----------------
__global__ void k_setup(const float* __restrict__ feat) {
    __shared__ float rowg[Hh];
    int tid = threadIdx.x;
    for (int i = tid; i < Hh * Hh; i += 256) {
        float d = (float)(i / Hh) - (float)(i % Hh);
        g_G[i] = __expf(-d * d * INV2G2);
    }
    __syncthreads();
    if (tid < Hh) {
        float s = 0.f;
        for (int b = 0; b < Hh; b++) s += g_G[tid * Hh + b];
        rowg[tid] = s;
    }
    __syncthreads();
    const float ca = sqrtf(INV2A2), cb = sqrtf(INV2B2);
    for (int i = tid; i < NN; i += 256) {
        int y = i / Ww, x = i - y * Ww;
        g_norms[i] = rowg[y] * rowg[x];
        float f0 = feat[3 * i], f1 = feat[3 * i + 1], f2 = feat[3 * i + 2];
        g_pix0[i] = make_float4((float)y * ca, (float)x * ca, f0 * cb, f1 * cb);
        g_pix1[i] = f2 * cb;
    }
}

// ---------------- build Kb (fp16) + row sums ----------------
__global__ __launch_bounds__(256) void k_build() {
    __shared__ float4 s_p0[TJ];
    __shared__ float  s_p1[TJ];
    __shared__ float  red[256];
    int tid = threadIdx.x;
    int i0 = blockIdx.x * BROWS;
    float4 p0[BROWS]; float p1[BROWS];
#pragma unroll
    for (int r = 0; r < BROWS; r++) { p0[r] = g_pix0[i0 + r]; p1[r] = g_pix1[i0 + r]; }
    float rsum[BROWS];
#pragma unroll
    for (int r = 0; r < BROWS; r++) rsum[r] = 0.f;

    for (int jt = 0; jt < NN; jt += TJ) {
        for (int e = tid; e < TJ; e += 256) { s_p0[e] = g_pix0[jt + e]; s_p1[e] = g_pix1[jt + e]; }
        __syncthreads();
        for (int jj = tid; jj < TJ / 2; jj += 256) {
            float4 qa = s_p0[2 * jj], qb = s_p0[2 * jj + 1];
            float  ra = s_p1[2 * jj], rb = s_p1[2 * jj + 1];
            int jph = (jt >> 1) + jj;
#pragma unroll
            for (int r = 0; r < BROWS; r++) {
                float d0 = p0[r].x - qa.x, d1 = p0[r].y - qa.y, d2 = p0[r].z - qa.z,
                      d3 = p0[r].w - qa.w, d4 = p1[r] - ra;
                float va = __expf(-(d0*d0 + d1*d1 + d2*d2 + d3*d3 + d4*d4));
                d0 = p0[r].x - qb.x; d1 = p0[r].y - qb.y; d2 = p0[r].z - qb.z;
                d3 = p0[r].w - qb.w; d4 = p1[r] - rb;
                float vb = __expf(-(d0*d0 + d1*d1 + d2*d2 + d3*d3 + d4*d4));
                __half ha = __float2half_rn(va), hb = __float2half_rn(vb);
                rsum[r] += __half2float(ha) + __half2float(hb);
                ((__half2*)(g_Kbh + (size_t)(i0 + r) * NN))[jph] = __halves2half2(ha, hb);
            }
        }
        __syncthreads();
    }
#pragma unroll
    for (int r = 0; r < BROWS; r++) {
        red[tid] = rsum[r];
        __syncthreads();
        for (int o = 128; o; o >>= 1) { if (tid < o) red[tid] += red[tid + o]; __syncthreads(); }
        if (!tid) g_normb[i0 + r] = red[0];
        __syncthreads();
    }
}

// ---------------- init: unary transpose + first softmax ----------------
__global__ void k_init(const float* __restrict__ un) {
    int n = blockIdx.x * blockDim.x + threadIdx.x;
    if (n >= NN) return;
    float v[CC], mx = -1e30f;
#pragma unroll
    for (int c = 0; c < CC; c++) { v[c] = un[n * CC + c]; g_unary[c * NN + n] = v[c]; mx = fmaxf(mx, v[c]); }
    float s = 0.f;
#pragma unroll
    for (int c = 0; c < CC; c++) { v[c] = __expf(v[c] - mx); s += v[c]; }
    float inv = 1.f / s;
#pragma unroll
    for (int c = 0; c < CC; c++) {
        float p = v[c] * inv;
        __half ph = __float2half_rn(p);
#pragma unroll
        for (int l = 0; l < LL; l++) {
            g_sm[(size_t)(l * CC + c) * NN + n] = p;
            g_smh[(l * CC + c) * NN + n] = ph;
        }
    }
}

__device__ __forceinline__ int rowmap(int r) { return (r / 5) * CC + (r % 5); }

// ---------------- fused separable spatial filter (one block per row r) ----------------
__global__ __launch_bounds__(512) void k_spat() {
    __shared__ float s_src[NN];
    __shared__ float s_tmp[NN];
    int tid = threadIdx.x;
    int r = blockIdx.x;
    const float* src = g_sm + (size_t)rowmap(r) * NN;
    for (int i = tid; i < NN; i += 512) s_src[i] = src[i];
    __syncthreads();
    // y-pass: tmp[y][x] = sum_yp G[y,yp] * src[yp][x]
    for (int i = tid; i < NN; i += 512) {
        int y = i / Ww, x = i - y * Ww;
        const float* grow = g_G + y * Hh;
        float s = 0.f;
#pragma unroll 8
        for (int yp = 0; yp < Hh; yp++) s += grow[yp] * s_src[yp * Ww + x];
        s_tmp[i] = s;
    }
    __syncthreads();
    // x-pass (G symmetric: G[x,xp]=G[xp,x] -> coalesced across lanes)
    for (int i = tid; i < NN; i += 512) {
        int y = i / Ww, x = i - y * Ww;
        const float* trow = s_tmp + y * Ww;
        float s = 0.f;
#pragma unroll 8
        for (int xp = 0; xp < Hh; xp++) s += g_G[xp * Hh + x] * trow[xp];
        g_Ssp[(size_t)r * NN + i] = s / g_norms[i];
    }
}

// ---------------- tensor-core bilateral GEMM, cp.async 2-stage pipeline ----------------
__global__ __launch_bounds__(256, 3) void k_gemm() {
    __shared__ __align__(16) __half s_a[2][MP * 64];     // 2 x 6 KB
    __shared__ __align__(16) __half s_b[2][64 * JB];     // 2 x 16 KB
    int tid = threadIdx.x, w = tid >> 5, lane = tid & 31;
    int j0 = blockIdx.x * JB;
    int kbase = blockIdx.y * KC;

    float acc[3][2][4];
#pragma unroll
    for (int mt = 0; mt < 3; mt++)
#pragma unroll
        for (int nt = 0; nt < 2; nt++)
#pragma unroll
            for (int i = 0; i < 4; i++) acc[mt][nt][i] = 0.f;

    int lrow = ((lane >> 3) & 1) * 8 + (lane & 7);
    int lhi  = (lane >> 4) & 1;

    // per-thread staging coordinates
    int ar = tid >> 3, ac = tid & 7;                 // A: thread covers rows ar, ar+32 (chunk ac)
    int br0 = tid >> 4, bc = tid & 15;               // B: rows br0 + {0,16,32,48}

    auto stage = [&](int ko, int buf) {
        int k0 = kbase + ko * 64;
        unsigned sa = su32(s_a[buf]), sb = su32(s_b[buf]);
        // A: 48 rows x 8 chunks = 384; 256 threads -> rows tid>>3 (0..31) and +32 for tid<128
        cpa16(sa + (unsigned)(ar * 64 + ((ac ^ (ar & 7)) << 3)) * 2u,
              g_smh + (size_t)ar * NN + k0 + ac * 8);
        if (tid < 128) {
            int r2 = ar + 32;
            cpa16(sa + (unsigned)(r2 * 64 + ((ac ^ (r2 & 7)) << 3)) * 2u,
                  g_smh + (size_t)r2 * NN + k0 + ac * 8);
        }
        // B: 64 rows x 16 chunks = 1024; 4 per thread
#pragma unroll
        for (int rr = 0; rr < 4; rr++) {
            int r = br0 + rr * 16;
            cpa16(sb + (unsigned)(r * JB + ((bc ^ (r & 7)) << 3)) * 2u,
                  g_Kbh + (size_t)(k0 + r) * NN + j0 + bc * 8);
        }
    };

    stage(0, 0);
    asm volatile("cp.async.commit_group;");
    stage(1, 1);
    asm volatile("cp.async.commit_group;");

    for (int ko = 0; ko < NST; ko++) {
        asm volatile("cp.async.wait_group 1;");
        __syncthreads();
        int buf = ko & 1;
        unsigned sa0 = su32(s_a[buf]), sb0 = su32(s_b[buf]);
#pragma unroll
        for (int kt = 0; kt < 4; kt++) {
            unsigned b[4];
            {
                int kl = kt * 16 + lrow;
                int c = 2 * w + lhi;
                unsigned addr = sb0 + (unsigned)(kl * JB + ((c ^ (kl & 7)) << 3)) * 2u;
                asm volatile("ldmatrix.sync.aligned.m8n8.x4.trans.shared.b16 {%0,%1,%2,%3}, [%4];"
                             : "=r"(b[0]), "=r"(b[1]), "=r"(b[2]), "=r"(b[3]) : "r"(addr));
            }
#pragma unroll
            for (int mt = 0; mt < 3; mt++) {
                unsigned a[4];
                int r = mt * 16 + lrow;
                int c = kt * 2 + lhi;
                unsigned addr = sa0 + (unsigned)(r * 64 + ((c ^ (r & 7)) << 3)) * 2u;
                asm volatile("ldmatrix.sync.aligned.m8n8.x4.shared.b16 {%0,%1,%2,%3}, [%4];"
                             : "=r"(a[0]), "=r"(a[1]), "=r"(a[2]), "=r"(a[3]) : "r"(addr));
#pragma unroll
                for (int nt = 0; nt < 2; nt++) {
                    asm volatile(
                        "mma.sync.aligned.m16n8k16.row.col.f32.f16.f16.f32 "
                        "{%0,%1,%2,%3}, {%4,%5,%6,%7}, {%8,%9}, {%0,%1,%2,%3};"
                        : "+f"(acc[mt][nt][0]), "+f"(acc[mt][nt][1]),
                          "+f"(acc[mt][nt][2]), "+f"(acc[mt][nt][3])
                        : "r"(a[0]), "r"(a[1]), "r"(a[2]), "r"(a[3]),
                          "r"(b[2 * nt]), "r"(b[2 * nt + 1]));
                }
            }
        }
        __syncthreads();
        if (ko + 2 < NST) stage(ko + 2, buf);
        asm volatile("cp.async.commit_group;");
    }

#pragma unroll
    for (int mt = 0; mt < 3; mt++) {
#pragma unroll
        for (int nt = 0; nt < 2; nt++) {
            int row = mt * 16 + (lane >> 2);
            int col = j0 + w * 16 + nt * 8 + (lane & 3) * 2;
            if (row < MR)
                *(float2*)(g_part + ((size_t)blockIdx.y * MR + row) * NN + col) =
                    make_float2(acc[mt][nt][0], acc[mt][nt][1]);
            if (row + 8 < MR)
                *(float2*)(g_part + ((size_t)blockIdx.y * MR + row + 8) * NN + col) =
                    make_float2(acc[mt][nt][2], acc[mt][nt][3]);
        }
    }
}

// ---------------- update: reduce partials, mix weights, q, FUSED softmax ----------------
__global__ void k_update(const float* __restrict__ Wcomp, const float* __restrict__ WLG,
                         const float* __restrict__ Wsp, const float* __restrict__ Wbl,
                         int last) {
    __shared__ float sC[36], sL[36], sS[36], sB[36];
    int tid = threadIdx.x;
    if (tid < 36) { sC[tid] = Wcomp[tid]; sL[tid] = WLG[tid]; sS[tid] = Wsp[tid]; sB[tid] = Wbl[tid]; }
    __syncthreads();
    int idx = blockIdx.x * blockDim.x + tid;
    if (idx >= LL * NN) return;
    int l = idx / NN, n = idx - l * NN;
    float invnb = 1.f / g_normb[n];
    float ssp[CC], sb[CC];
    float tsp = 0.f;
#pragma unroll
    for (int c2 = 0; c2 < CC; c2++) {
        size_t ro = (size_t)(l * CC + c2) * NN + n;
        float s = 0.f;
#pragma unroll
        for (int z = 0; z < KSPLIT; z++) s += g_part[(size_t)z * MR * NN + ro];
        sb[c2] = s * invnb;
    }
#pragma unroll
    for (int c2 = 0; c2 < 5; c2++) {
        ssp[c2] = g_Ssp[(size_t)(l * 5 + c2) * NN + n];
        tsp += ssp[c2];
    }
    ssp[5] = 1.f - tsp;
    float msg[CC];
#pragma unroll
    for (int c = 0; c < CC; c++) {
        float m = 0.f;
#pragma unroll
        for (int c2 = 0; c2 < CC; c2++)
            m += sS[c * CC + c2] * ssp[c2] + sB[c * CC + c2] * sb[c2];
        msg[c] = m;
    }
    if (last) {
        // final iter: store msg for ELBO, keep g_sm (= softmax of pre-update q)
#pragma unroll
        for (int c = 0; c < CC; c++) g_msg[(size_t)(l * CC + c) * NN + n] = msg[c];
        return;
    }
    float q[CC], mx = -1e30f;
#pragma unroll
    for (int c = 0; c < CC; c++) {
        float pw = 0.f;
#pragma unroll
        for (int c2 = 0; c2 < CC; c2++) pw += sC[c * CC + c2] * msg[c2];
        q[c] = g_unary[c * NN + n] + sL[c * CC + l] - pw;
        mx = fmaxf(mx, q[c]);
    }
    float s = 0.f;
#pragma unroll
    for (int c = 0; c < CC; c++) { q[c] = __expf(q[c] - mx); s += q[c]; }
    float inv = 1.f / s;
#pragma unroll
    for (int c = 0; c < CC; c++) {
        float p = q[c] * inv;
        g_sm[(size_t)(l * CC + c) * NN + n] = p;
        g_smh[(l * CC + c) * NN + n] = __float2half_rn(p);
    }
}

// ---------------- final ELBO ----------------
__global__ void k_elbo(const float* __restrict__ WLG, float* __restrict__ out) {
    __shared__ float sL[36];
    __shared__ float red[256];
    int l = blockIdx.x, tid = threadIdx.x;
    if (tid < 36) sL[tid] = WLG[tid];
    __syncthreads();
    float acc = 0.f;
    for (int i = tid; i < CC * NN; i += 256) {
        int c = i / NN;
        float s = g_sm[(size_t)l * CC * NN + i];
        float u = g_unary[i];
        float m = g_msg[(size_t)l * CC * NN + i];
        acc += s * (u + sL[c * CC + l] - m) - s * __logf(s + 1e-10f);
    }
    red[tid] = acc;
    __syncthreads();
    for (int o = 128; o; o >>= 1) { if (tid < o) red[tid] += red[tid + o]; __syncthreads(); }
    if (!tid) out[l] = red[0];
}

// ---------------- launch ----------------
extern "C" void kernel_launch(void* const* d_in, const int* in_sizes, int n_in,
                              void* d_out, int out_size) {
    const float* unary = (const float*)d_in[0];
    const float* feat  = (const float*)d_in[1];
    const float* Wcomp = (const float*)d_in[2];
    const float* WLG   = (const float*)d_in[3];
    const float* Wsp   = (const float*)d_in[4];
    const float* Wbl   = (const float*)d_in[5];
    float* out = (float*)d_out;

    k_setup<<<1, 256>>>(feat);                 // 1
    k_build<<<NN / BROWS, 256>>>();            // 2
    k_init<<<25, 256>>>(unary);                // 3

    for (int it = 0; it < NITER; it++) {
        k_gemm<<<dim3(NN / JB, KSPLIT), 256>>>();          // 4 at it==0 -> profiled
        k_spat<<<CR, 512>>>();
        k_update<<<150, 256>>>(Wcomp, WLG, Wsp, Wbl, it == NITER - 1);
    }
    k_elbo<<<LL, 256>>>(WLG, out);
}